// round 3
// baseline (speedup 1.0000x reference)
#include <cuda_runtime.h>
#include <math.h>

// SmoothLDDTLoss — B=2, N=4096.
//
// Simplification: reference's c_lm = (dGT<30) | nuc | ((dGT<15) | ~nuc) contains
// (nuc | ~nuc) == True, so c_lm == ~eye(N): every off-diagonal pair counts;
// is_dna/is_rna are dead inputs.
//   loss = 1 - [ sum_{l!=m} 0.25*(sig(.5-d)+sig(1-d)+sig(2-d)+sig(4-d)) ] / (B*N*(N-1))
//   d = | ||xGT_l-xGT_m||^2 - ||x_l-x_m||^2 |
// eps symmetric: compute strict upper triangle, double it.
//
// Sigmoid-sum as one rational in e = exp(d):
//   S(e) = (s1 e^3 + 2 s2 e^2 + 3 s3 e + 4 s4) / (e^4 + s1 e^3 + s2 e^2 + s3 e + s4)
// s_k = elementary symmetric polys of {e^0.5, e^1, e^2, e^4}. 1 EX2 + 1 RCP per pair.
// d clamped to 21 so e^4 stays finite in fp32 (contribution error < 1e-7).
//
// Mainloop in packed f32x2 (1 row x 2 columns per thread) — 2 flops/issue on
// the FMA pipe; ptxas never emits FFMA2 from C++, so inline PTX.

#define TILE 128
#define NTHREADS 256
#define MAX_BLOCKS 4096

__device__ float g_partials[MAX_BLOCKS];

typedef unsigned long long u64;

__device__ __forceinline__ u64 pk2(float lo, float hi) {
    u64 r; asm("mov.b64 %0, {%1, %2};" : "=l"(r) : "f"(lo), "f"(hi)); return r;
}
__device__ __forceinline__ void upk2(u64 v, float& lo, float& hi) {
    asm("mov.b64 {%0, %1}, %2;" : "=f"(lo), "=f"(hi) : "l"(v));
}
__device__ __forceinline__ u64 f2add(u64 a, u64 b) {
    u64 r; asm("add.rn.f32x2 %0, %1, %2;" : "=l"(r) : "l"(a), "l"(b)); return r;
}
__device__ __forceinline__ u64 f2mul(u64 a, u64 b) {
    u64 r; asm("mul.rn.f32x2 %0, %1, %2;" : "=l"(r) : "l"(a), "l"(b)); return r;
}
__device__ __forceinline__ u64 f2fma(u64 a, u64 b, u64 c) {
    u64 r; asm("fma.rn.f32x2 %0, %1, %2, %3;" : "=l"(r) : "l"(a), "l"(b), "l"(c)); return r;
}
__device__ __forceinline__ float ex2a(float x) {
    float r; asm("ex2.approx.f32 %0, %1;" : "=f"(r) : "f"(x)); return r;
}
__device__ __forceinline__ float rcpa(float x) {
    float r; asm("rcp.approx.f32 %0, %1;" : "=f"(r) : "f"(x)); return r;
}

__global__ __launch_bounds__(NTHREADS) void lddt_tile_kernel(
    const float* __restrict__ x,   // [B, N, 3]
    const float* __restrict__ g,   // [B, N, 3]
    int N, int tilesPerBatch, int T)
{
    // Column tile: 64 column-pairs x 6 attrs, pre-negated, packed as f32x2.
    // scolp[p][a] = { -attr_a(col 2p), -attr_a(col 2p+1) }, attrs: bx,by,bz,hx,hy,hz
    __shared__ u64 scolp[64][6];
    __shared__ float warpSums[NTHREADS / 32];

    const int id = blockIdx.x;
    const int b = id / tilesPerBatch;
    int rem = id % tilesPerBatch;
    int ti = 0;
    while (rem >= T - ti) { rem -= T - ti; ti++; }   // triangular decode, ti <= tj
    const int tj = ti + rem;

    const int t = threadIdx.x;
    const long rowBase = (long)(b * N + ti * TILE) * 3;
    const long colBase = (long)(b * N + tj * TILE) * 3;

    // Stage negated, packed column coords.
    for (int p = t; p < 64; p += NTHREADS) {
        const float* c0x = x + colBase + (2 * p) * 3;
        const float* c1x = x + colBase + (2 * p + 1) * 3;
        const float* c0g = g + colBase + (2 * p) * 3;
        const float* c1g = g + colBase + (2 * p + 1) * 3;
        scolp[p][0] = pk2(-c0x[0], -c1x[0]);
        scolp[p][1] = pk2(-c0x[1], -c1x[1]);
        scolp[p][2] = pk2(-c0x[2], -c1x[2]);
        scolp[p][3] = pk2(-c0g[0], -c1g[0]);
        scolp[p][4] = pk2(-c0g[1], -c1g[1]);
        scolp[p][5] = pk2(-c0g[2], -c1g[2]);
    }
    __syncthreads();

    // Thread layout: row r = t & 127 (register-resident, broadcast-packed);
    // column-pairs p = (t>>7) + 2k, k = 0..31 — warp-uniform smem broadcast.
    const int r = t & 127;
    const int q = t >> 7;

    const float* rx = x + rowBase + r * 3;
    const float* rg = g + rowBase + r * 3;
    const u64 AX = pk2(rx[0], rx[0]);
    const u64 AY = pk2(rx[1], rx[1]);
    const u64 AZ = pk2(rx[2], rx[2]);
    const u64 GX = pk2(rg[0], rg[0]);
    const u64 GY = pk2(rg[1], rg[1]);
    const u64 GZ = pk2(rg[2], rg[2]);

    // Rational coefficients (both lanes identical).
    const float S1 = 66.35420923f, S2 = 678.6088038f, S3 = 2039.582176f, S4 = 1808.042414f;
    const float P3 = 66.35420923f, P2 = 1357.217608f, P1 = 6118.746527f, P0 = 7232.169658f;
    const u64 S1v = pk2(S1, S1), S2v = pk2(S2, S2), S3v = pk2(S3, S3), S4v = pk2(S4, S4);
    const u64 P3v = pk2(P3, P3), P2v = pk2(P2, P2), P1v = pk2(P1, P1), P0v = pk2(P0, P0);
    const u64 NEG1 = pk2(-1.0f, -1.0f);
    const float L2E = 1.44269504f;

    u64 accv = pk2(0.0f, 0.0f);
    float accs = 0.0f;                 // scalar acc for masked diagonal path

    if (ti != tj) {
        // Off-diagonal tile: all pairs are strict-upper. Unmasked vector path.
#pragma unroll 4
        for (int k = 0; k < 32; k++) {
            const int p = q + 2 * k;
            const u64 cbx = scolp[p][0], cby = scolp[p][1], cbz = scolp[p][2];
            const u64 chx = scolp[p][3], chy = scolp[p][4], chz = scolp[p][5];

            u64 dxx = f2add(AX, cbx), dxy = f2add(AY, cby), dxz = f2add(AZ, cbz);
            u64 dgx = f2add(GX, chx), dgy = f2add(GY, chy), dgz = f2add(GZ, chz);
            u64 dx2 = f2fma(dxz, dxz, f2fma(dxy, dxy, f2mul(dxx, dxx)));
            u64 dg2 = f2fma(dgz, dgz, f2fma(dgy, dgy, f2mul(dgx, dgx)));
            u64 h = f2fma(dx2, NEG1, dg2);          // dg2 - dx2 (per lane)

            float h0, h1; upk2(h, h0, h1);
            float e0 = ex2a(fminf(fabsf(h0), 21.0f) * L2E);
            float e1 = ex2a(fminf(fabsf(h1), 21.0f) * L2E);
            u64 e = pk2(e0, e1);

            u64 P = f2fma(f2fma(f2fma(P3v, e, P2v), e, P1v), e, P0v);
            u64 Q = f2fma(f2fma(f2fma(f2add(e, S1v), e, S2v), e, S3v), e, S4v);
            float q0, q1; upk2(Q, q0, q1);
            u64 R = pk2(rcpa(q0), rcpa(q1));
            accv = f2fma(P, R, accv);
        }
    } else {
        // Diagonal tile: keep only strict-upper (r < m) contributions.
#pragma unroll 4
        for (int k = 0; k < 32; k++) {
            const int p = q + 2 * k;
            const int m0 = 2 * p, m1 = 2 * p + 1;
            const u64 cbx = scolp[p][0], cby = scolp[p][1], cbz = scolp[p][2];
            const u64 chx = scolp[p][3], chy = scolp[p][4], chz = scolp[p][5];

            u64 dxx = f2add(AX, cbx), dxy = f2add(AY, cby), dxz = f2add(AZ, cbz);
            u64 dgx = f2add(GX, chx), dgy = f2add(GY, chy), dgz = f2add(GZ, chz);
            u64 dx2 = f2fma(dxz, dxz, f2fma(dxy, dxy, f2mul(dxx, dxx)));
            u64 dg2 = f2fma(dgz, dgz, f2fma(dgy, dgy, f2mul(dgx, dgx)));
            u64 h = f2fma(dx2, NEG1, dg2);

            float h0, h1; upk2(h, h0, h1);
            float e0 = ex2a(fminf(fabsf(h0), 21.0f) * L2E);
            float e1 = ex2a(fminf(fabsf(h1), 21.0f) * L2E);
            u64 e = pk2(e0, e1);

            u64 P = f2fma(f2fma(f2fma(P3v, e, P2v), e, P1v), e, P0v);
            u64 Q = f2fma(f2fma(f2fma(f2add(e, S1v), e, S2v), e, S3v), e, S4v);
            float q0, q1; upk2(Q, q0, q1);
            u64 s = f2mul(P, pk2(rcpa(q0), rcpa(q1)));
            float s0, s1; upk2(s, s0, s1);
            accs += (r < m0) ? s0 : 0.0f;
            accs += (r < m1) ? s1 : 0.0f;
        }
    }

    float a0, a1; upk2(accv, a0, a1);
    float acc = a0 + a1 + accs;

#pragma unroll
    for (int off = 16; off > 0; off >>= 1)
        acc += __shfl_down_sync(0xFFFFFFFFu, acc, off);
    if ((t & 31) == 0) warpSums[t >> 5] = acc;
    __syncthreads();
    if (t == 0) {
        float blockSum = 0.0f;
#pragma unroll
        for (int w = 0; w < NTHREADS / 32; w++) blockSum += warpSums[w];
        g_partials[blockIdx.x] = blockSum;     // deterministic: no atomics
    }
}

// Deterministic reduction: fixed strided order + fixed smem tree.
__global__ __launch_bounds__(256) void finalize_kernel(float* out, int n, double invCount)
{
    __shared__ double sd[256];
    const int t = threadIdx.x;
    double s = 0.0;
    for (int i = t; i < n; i += 256) s += (double)g_partials[i];
    sd[t] = s;
    __syncthreads();
#pragma unroll
    for (int off = 128; off > 0; off >>= 1) {
        if (t < off) sd[t] += sd[t + off];
        __syncthreads();
    }
    if (t == 0) {
        // sum over l!=m = 2 * upper-triangle; eps carries the 0.25 factor.
        double lddt = 0.5 * sd[0] * invCount;   // 2 * 0.25 = 0.5
        out[0] = (float)(1.0 - lddt);
    }
}

extern "C" void kernel_launch(void* const* d_in, const int* in_sizes, int n_in,
                              void* d_out, int out_size)
{
    const float* x = (const float*)d_in[0];   // x_l   [B,N,3] f32
    const float* g = (const float*)d_in[1];   // xGT_l [B,N,3] f32
    // d_in[2]/d_in[3] (is_dna/is_rna) provably unused: c_lm == ~eye.

    const int B = 2;
    const int N = in_sizes[0] / (3 * B);        // 4096
    const int T = N / TILE;                     // 32
    const int tilesPerBatch = T * (T + 1) / 2;  // 528
    const int grid = B * tilesPerBatch;         // 1056

    float* out = (float*)d_out;
    double invCount = 1.0 / ((double)B * (double)N * (double)(N - 1));

    lddt_tile_kernel<<<grid, NTHREADS>>>(x, g, N, tilesPerBatch, T);
    finalize_kernel<<<1, 256>>>(out, grid, invCount);
}